// round 16
// baseline (speedup 1.0000x reference)
#include <cuda_runtime.h>
#include <cuda_bf16.h>
#include <cuda_fp16.h>
#include <cstdint>

#define Bb 4
#define Tt 2048
#define Cc 1024
#define Hh 16
#define HDm 64

// ---------------- scratch ------------------------------------------------
__device__ __half g_qkv16[(size_t)Bb * Tt * 3 * Cc];   // [8192, 3072] fp16
__device__ __half g_x16[(size_t)Bb * Tt * Cc];
__device__ __half g_y16[(size_t)Bb * Tt * Cc];
__device__ __half g_wa16[(size_t)3 * Cc * Cc];          // [3072,1024] (N,K) fp16
__device__ __half g_wp16[(size_t)Cc * Cc];              // [1024,1024] (N,K) fp16

// q pre-scale: 1/sqrt(64) * log2(e)  (softmax runs in exp2 domain)
#define QSCALE 0.180336880f

// ---------------- helpers ------------------------------------------------
__device__ __forceinline__ uint32_t smem_u32(const void* p) {
    return (uint32_t)__cvta_generic_to_shared(p);
}
__device__ __forceinline__ void cp_async16(uint32_t dst, const void* src) {
    asm volatile("cp.async.cg.shared.global [%0], [%1], 16;\n"
                 :: "r"(dst), "l"(src));
}
#define CP_COMMIT() asm volatile("cp.async.commit_group;\n" ::: "memory")
#define CP_WAIT1()  asm volatile("cp.async.wait_group 1;\n" ::: "memory")

#define LDSM4(r0, r1, r2, r3, addr) \
    asm volatile("ldmatrix.sync.aligned.m8n8.x4.shared.b16 {%0,%1,%2,%3}, [%4];" \
                 : "=r"(r0), "=r"(r1), "=r"(r2), "=r"(r3) : "r"(addr))
#define LDSM4T(r0, r1, r2, r3, addr) \
    asm volatile("ldmatrix.sync.aligned.m8n8.x4.trans.shared.b16 {%0,%1,%2,%3}, [%4];" \
                 : "=r"(r0), "=r"(r1), "=r"(r2), "=r"(r3) : "r"(addr))

// fp16 mma, fp32 accumulate
#define MMAH(d, a, bv0, bv1) \
    asm volatile("mma.sync.aligned.m16n8k16.row.col.f32.f16.f16.f32 " \
                 "{%0,%1,%2,%3}, {%4,%5,%6,%7}, {%8,%9}, {%0,%1,%2,%3};" \
                 : "+f"((d)[0]), "+f"((d)[1]), "+f"((d)[2]), "+f"((d)[3]) \
                 : "r"((a)[0]), "r"((a)[1]), "r"((a)[2]), "r"((a)[3]), \
                   "r"(bv0), "r"(bv1))

__device__ __forceinline__ uint32_t packf16(float hi, float lo) {
    uint32_t d;
    asm("cvt.rn.f16x2.f32 %0, %1, %2;" : "=r"(d) : "f"(hi), "f"(lo));
    return d;
}
__device__ __forceinline__ uint32_t h2exp2(uint32_t x) {
    uint32_t d;
    asm("ex2.approx.f16x2 %0, %1;" : "=r"(d) : "r"(x));
    return d;
}

// ---------------- merged input prep ----------------------------------------
__global__ __launch_bounds__(256)
void prep_inputs(const float4* __restrict__ x4, __half* __restrict__ x16,
                 const float* __restrict__ wa, __half* __restrict__ wa16,
                 const float* __restrict__ wp, __half* __restrict__ wp16)
{
    __shared__ float t[32][33];
    const int bid = blockIdx.x;
    const int tid = threadIdx.x;

    if (bid < 8192) {
        int i = bid * 256 + tid;
        float4 v = x4[i];
        *(uint2*)(x16 + (size_t)i * 4) =
            make_uint2(packf16(v.y, v.x), packf16(v.w, v.z));
        return;
    }

    const float* in;
    __half* o16;
    int N, bx, by;
    if (bid < 11264) {
        int b2 = bid - 8192;
        in = wa; o16 = wa16; N = 3 * Cc;
        bx = b2 % 96; by = b2 / 96;
    } else {
        int b3 = bid - 11264;
        in = wp; o16 = wp16; N = Cc;
        bx = b3 % 32; by = b3 / 32;
    }
    const int tx = tid & 31;
    const int ty = tid >> 5;
    int xg = bx * 32 + tx;
    int yg = by * 32 + ty;
#pragma unroll
    for (int j = 0; j < 32; j += 8)
        t[ty + j][tx] = in[(size_t)(yg + j) * N + xg];
    __syncthreads();
    int xo = by * 32 + tx;
    int yo = bx * 32 + ty;
#pragma unroll
    for (int j = 0; j < 32; j += 8)
        o16[(size_t)(yo + j) * Cc + xo] = __float2half_rn(t[tx][ty + j]);
}

// ---------------- mma.sync fp16 GEMM (converged; unchanged) -----------------
template <int Mdim, int Ndim, int Kdim, int OM>
__global__ __launch_bounds__(256, 2)
void gemm_mma(const __half* __restrict__ A,
              const __half* __restrict__ Bw,
              const float* __restrict__ bias, float* __restrict__ C,
              __half* __restrict__ Ch)
{
    constexpr int NCHUNK = Kdim / 64;
    constexpr uint32_t MATB = 16384;
    constexpr uint32_t STAGE = 32768;

    extern __shared__ char smem[];
    const uint32_t sbase = smem_u32(smem);

    const int tid  = threadIdx.x;
    const int wid  = tid >> 5;
    const int lane = tid & 31;
    const int m0 = blockIdx.y * 128;
    const int n0 = blockIdx.x * 128;
    const int wm = (wid & 3) * 32;
    const int wn = (wid >> 2) * 64;

    const int arow = lane & 15;
    const int ac16 = lane >> 4;
    const int bn   = ((lane >> 4) << 3) + (lane & 7);
    const int bc16 = (lane >> 3) & 1;

    auto swz = [](int row, int c16) -> uint32_t {
        return (uint32_t)row * 128 + (uint32_t)((c16 ^ (row & 7)) << 4);
    };

    auto load_chunk = [&](int c, int st) {
        const int k0 = c * 64;
        const uint32_t sb = sbase + (uint32_t)st * STAGE;
#pragma unroll
        for (int t = 0; t < 8; t++) {
            int i = tid + t * 256;
            int mat = i >> 10;
            int rem = i & 1023;
            int row = rem >> 3, seg = rem & 7;
            uint32_t dst = sb + (uint32_t)mat * MATB + swz(row, seg);
            const __half* src = (mat == 0)
                ? A + (size_t)(m0 + row) * Kdim + k0 + seg * 8
                : Bw + (size_t)(n0 + row) * Kdim + k0 + seg * 8;
            cp_async16(dst, src);
        }
    };

    float acc[2][8][4];
#pragma unroll
    for (int i = 0; i < 2; i++)
#pragma unroll
        for (int j = 0; j < 8; j++)
#pragma unroll
            for (int k = 0; k < 4; k++) acc[i][j][k] = 0.f;

    load_chunk(0, 0); CP_COMMIT();
    load_chunk(1, 1); CP_COMMIT();

    for (int c = 0; c < NCHUNK; c++) {
        CP_WAIT1();
        __syncthreads();
        if (c + 2 < NCHUNK) load_chunk(c + 2, (c + 2) % 3);
        CP_COMMIT();

        const uint32_t sb = sbase + (uint32_t)(c % 3) * STAGE;
        const uint32_t sA = sb, sB = sb + MATB;

        uint32_t af[2][4], bf[8][2];
#pragma unroll
        for (int ks = 0; ks < 4; ks++) {
#pragma unroll
            for (int mf = 0; mf < 2; mf++) {
                int row = wm + mf * 16 + arow;
                uint32_t ra = swz(row, ks * 2 + ac16);
                LDSM4(af[mf][0], af[mf][1], af[mf][2], af[mf][3], sA + ra);
            }
#pragma unroll
            for (int np = 0; np < 4; np++) {
                int row = wn + np * 16 + bn;
                uint32_t rb = swz(row, ks * 2 + bc16);
                LDSM4(bf[np * 2][0], bf[np * 2][1],
                      bf[np * 2 + 1][0], bf[np * 2 + 1][1], sB + rb);
            }
#pragma unroll
            for (int mf = 0; mf < 2; mf++)
#pragma unroll
                for (int nf = 0; nf < 8; nf++)
                    MMAH(acc[mf][nf], af[mf], bf[nf][0], bf[nf][1]);
        }
    }

    const int r0 = lane >> 2;
    const int c0 = (lane & 3) * 2;
#pragma unroll
    for (int mf = 0; mf < 2; mf++) {
#pragma unroll
        for (int nf = 0; nf < 8; nf++) {
            int row = m0 + wm + mf * 16 + r0;
            int col = n0 + wn + nf * 8 + c0;
            float2 b2 = *(const float2*)(bias + col);
            float y00 = acc[mf][nf][0] + b2.x;
            float y01 = acc[mf][nf][1] + b2.y;
            float y10 = acc[mf][nf][2] + b2.x;
            float y11 = acc[mf][nf][3] + b2.y;
            if (OM == 0) {
                *(float2*)(C + (size_t)row * Ndim + col) = make_float2(y00, y01);
                *(float2*)(C + (size_t)(row + 8) * Ndim + col) = make_float2(y10, y11);
            } else {
                float s = (col < Cc) ? QSCALE : 1.0f;
                *(uint32_t*)(Ch + (size_t)row * Ndim + col) =
                    packf16(y01 * s, y00 * s);
                *(uint32_t*)(Ch + (size_t)(row + 8) * Ndim + col) =
                    packf16(y11 * s, y10 * s);
            }
        }
    }
}

// ---------------- flash attention: fp16, Q tile 256, 512 threads ------------
// CTA: one (b, h, 256-row Q block). 512 threads, 16 warps x 16 q rows.
// Halves KV tile loads and barriers vs Q128 (per-warp math identical ->
// bit-identical results). 3-stage KV pipeline, np-skip, constant l-fragment.
// smem = Q(256x144=36864) + 3 x (K 9216 + V 9216) = 92160 -> 1 CTA/SM
// (16 warps/SM, same as before's 2x8).
__global__ __launch_bounds__(512, 1)
void flash_f16(const __half* __restrict__ qkv,
               __half* __restrict__ y16)
{
    constexpr uint32_t RSTR = 144;
    constexpr uint32_t TB   = 9216;
    constexpr uint32_t QB   = 36864;
    constexpr uint32_t KVSTG = 2 * TB;

    extern __shared__ char smem[];
    const uint32_t sbase = smem_u32(smem);

    const int tid  = threadIdx.x;
    const int wid  = tid >> 5;      // 0..15
    const int lane = tid & 31;
    const int qt   = (Tt / 256 - 1) - blockIdx.x;   // long CTAs first
    const int bh   = blockIdx.y;
    const int b    = bh >> 4;
    const int h    = bh & 15;
    const int wm   = wid * 16;                      // 0..240
    const int nkv  = 4 * qt + 4;                    // KV tiles of 64

    const size_t rs = 3 * Cc;
    const size_t rowbase = (size_t)b * Tt;

    auto loadKV = [&](int kt, int st) {
        const uint32_t kb = sbase + QB + (uint32_t)st * KVSTG;
        const uint32_t vb = kb + TB;
        // 512 segments over 512 threads: one K + one V cp.async each
        int r = tid >> 3, s = tid & 7;
        uint32_t off = (uint32_t)r * RSTR + s * 16;
        size_t gk = (rowbase + kt * 64 + r) * rs + Cc + h * HDm + s * 8;
        cp_async16(kb + off, qkv + gk);
        cp_async16(vb + off, qkv + gk + Cc);
    };

    {
#pragma unroll
        for (int i = tid; i < 2048; i += 512) {     // Q: 256 rows x 8 segs
            int r = i >> 3, s = i & 7;
            uint32_t off = (uint32_t)r * RSTR + s * 16;
            size_t gq = (rowbase + qt * 256 + r) * rs + h * HDm + s * 8;
            cp_async16(sbase + off, qkv + gq);
        }
        loadKV(0, 0);
    }
    CP_COMMIT();
    loadKV(1, 1);
    CP_COMMIT();

    CP_WAIT1();
    __syncthreads();

    uint32_t qf[4][4];
    {
        const int arow = lane & 15;
        const int ak16 = (lane >> 4) * 16;
#pragma unroll
        for (int ks = 0; ks < 4; ks++) {
            uint32_t ra = (uint32_t)(wm + arow) * RSTR + ks * 32 + ak16;
            LDSM4(qf[ks][0], qf[ks][1], qf[ks][2], qf[ks][3], sbase + ra);
        }
    }

    float o[8][4], oL[4];
#pragma unroll
    for (int i = 0; i < 8; i++)
#pragma unroll
        for (int j = 0; j < 4; j++) o[i][j] = 0.f;
#pragma unroll
    for (int j = 0; j < 4; j++) oL[j] = 0.f;

    const int gid = lane >> 2;
    const int tig = lane & 3;
    const int brow = ((lane >> 4) << 3) + (lane & 7);
    const int bk16 = (lane & 8) * 2;
    const int vrow = lane & 15;
    const int vcol16 = (lane >> 4) * 16;

    // constant ones-column B fragment: B[k][0]=1, B[k][1..7]=0 (n = lane>>2)
    const uint32_t wone = (lane < 4) ? 0x3c003c00u : 0u;

    const int rg0 = qt * 256 + wm + gid;
    const int rg1 = rg0 + 8;
    const int rwmax = qt * 256 + wm + 15;

    for (int kt = 0; kt < nkv; kt++) {
        CP_WAIT1();
        __syncthreads();
        if (kt + 2 < nkv) loadKV(kt + 2, (kt + 2) % 3);
        CP_COMMIT();

        const uint32_t sk = sbase + QB + (uint32_t)(kt % 3) * KVSTG;
        const uint32_t sv = sk + TB;

        if (kt * 64 <= rwmax) {      // skip tiles fully above this warp's rows
            const int npLim = (rwmax - kt * 64) >> 4;

            float s[8][4];
#pragma unroll
            for (int i = 0; i < 8; i++)
#pragma unroll
                for (int j = 0; j < 4; j++) s[i][j] = 0.f;

#pragma unroll
            for (int ks = 0; ks < 4; ks++) {
                const uint32_t kb = ks * 32;
#pragma unroll
                for (int np = 0; np < 4; np++) {
                    if (np <= npLim) {
                        uint32_t ro = (uint32_t)(np * 16 + brow) * RSTR + kb + bk16;
                        uint32_t b0, b1, b2, b3;
                        LDSM4(b0, b1, b2, b3, sk + ro);
                        MMAH(s[2 * np], qf[ks], b0, b1);
                        MMAH(s[2 * np + 1], qf[ks], b2, b3);
                    }
                }
            }

            if (kt * 64 + 63 > qt * 256 + wm) {   // diagonal-overlapping tile
#pragma unroll
                for (int nf = 0; nf < 8; nf++) {
                    int cc0 = kt * 64 + nf * 8 + tig * 2;
                    if (cc0 > rg0) s[nf][0] = -1e30f;
                    if (cc0 + 1 > rg0) s[nf][1] = -1e30f;
                    if (cc0 > rg1) s[nf][2] = -1e30f;
                    if (cc0 + 1 > rg1) s[nf][3] = -1e30f;
                }
            }

            // P = exp2(s) in packed fp16; O += P V; l += P @ ones
#pragma unroll
            for (int ks = 0; ks < 4; ks++) {
                uint32_t pf[4];
                pf[0] = h2exp2(packf16(s[2 * ks][1], s[2 * ks][0]));
                pf[1] = h2exp2(packf16(s[2 * ks][3], s[2 * ks][2]));
                pf[2] = h2exp2(packf16(s[2 * ks + 1][1], s[2 * ks + 1][0]));
                pf[3] = h2exp2(packf16(s[2 * ks + 1][3], s[2 * ks + 1][2]));
#pragma unroll
                for (int np = 0; np < 4; np++) {
                    uint32_t vo = (uint32_t)(ks * 16 + vrow) * RSTR + np * 32 + vcol16;
                    uint32_t v0, v1, v2, v3;
                    LDSM4T(v0, v1, v2, v3, sv + vo);
                    MMAH(o[2 * np], pf, v0, v1);
                    MMAH(o[2 * np + 1], pf, v2, v3);
                }
                MMAH(oL, pf, wone, wone);   // l column (constant fragment)
            }
        }
    }

    // broadcast l (held by tig=0 in oL[0]/oL[2]) to the whole row group
    float l0 = __shfl_sync(0xffffffffu, oL[0], (lane >> 2) << 2);
    float l1 = __shfl_sync(0xffffffffu, oL[2], (lane >> 2) << 2);

    float inv0 = 1.0f / l0, inv1 = 1.0f / l1;
    const size_t row0 = rowbase + qt * 256 + wm + gid;
    const int colb = h * HDm + tig * 2;
#pragma unroll
    for (int nh = 0; nh < 8; nh++) {
        int col = colb + nh * 8;
        *(uint32_t*)(y16 + row0 * Cc + col) =
            packf16(o[nh][1] * inv0, o[nh][0] * inv0);
        *(uint32_t*)(y16 + (row0 + 8) * Cc + col) =
            packf16(o[nh][3] * inv1, o[nh][2] * inv1);
    }
}

// ---------------- launch ---------------------------------------------------
extern "C" void kernel_launch(void* const* d_in, const int* in_sizes, int n_in,
                              void* d_out, int out_size)
{
    const float* x      = (const float*)d_in[0];
    const float* w_attn = (const float*)d_in[1];
    const float* b_attn = (const float*)d_in[2];
    const float* w_proj = (const float*)d_in[3];
    const float* b_proj = (const float*)d_in[4];
    float* out = (float*)d_out;

    __half *qkv16, *x16, *y16, *wa16, *wp16;
    cudaGetSymbolAddress((void**)&qkv16, g_qkv16);
    cudaGetSymbolAddress((void**)&x16, g_x16);
    cudaGetSymbolAddress((void**)&y16, g_y16);
    cudaGetSymbolAddress((void**)&wa16, g_wa16);
    cudaGetSymbolAddress((void**)&wp16, g_wp16);

    constexpr int GEMM_SMEM = 3 * 32768;  // 98304 -> 2 CTAs/SM
    cudaFuncSetAttribute(gemm_mma<Bb * Tt, 3 * Cc, Cc, 1>,
                         cudaFuncAttributeMaxDynamicSharedMemorySize, GEMM_SMEM);
    cudaFuncSetAttribute(gemm_mma<Bb * Tt, Cc, Cc, 0>,
                         cudaFuncAttributeMaxDynamicSharedMemorySize, GEMM_SMEM);
    constexpr int FLASH_SMEM = 36864 + 6 * 9216;  // 92160 -> 1 CTA/SM (16 warps)
    cudaFuncSetAttribute(flash_f16, cudaFuncAttributeMaxDynamicSharedMemorySize,
                         FLASH_SMEM);

    // 0) merged input prep: x->fp16 + both weight transposes (one launch)
    prep_inputs<<<12288, 256>>>((const float4*)x, x16, w_attn, wa16, w_proj, wp16);

    // 1) QKV GEMM (fp16) -> fp16 qkv, q pre-scaled by QSCALE
    gemm_mma<Bb * Tt, 3 * Cc, Cc, 1>
        <<<dim3((3 * Cc) / 128, (Bb * Tt) / 128), 256, GEMM_SMEM>>>(
            x16, wa16, b_attn, nullptr, qkv16);

    // 2) flash attention (fp16, Q tile 256) -> fp16 y
    flash_f16<<<dim3(Tt / 256, Bb * Hh), 512, FLASH_SMEM>>>(qkv16, y16);

    // 3) output projection (fp16) -> fp32 out
    gemm_mma<Bb * Tt, Cc, Cc, 0>
        <<<dim3(Cc / 128, (Bb * Tt) / 128), 256, GEMM_SMEM>>>(
            y16, wp16, b_proj, out, nullptr);
}

// round 17
// speedup vs baseline: 1.0072x; 1.0072x over previous
#include <cuda_runtime.h>
#include <cuda_bf16.h>
#include <cuda_fp16.h>
#include <cstdint>

#define Bb 4
#define Tt 2048
#define Cc 1024
#define Hh 16
#define HDm 64

// ---------------- scratch ------------------------------------------------
__device__ __half g_qkv16[(size_t)Bb * Tt * 3 * Cc];   // [8192, 3072] fp16
__device__ __half g_x16[(size_t)Bb * Tt * Cc];
__device__ __half g_y16[(size_t)Bb * Tt * Cc];
__device__ __half g_wa16[(size_t)3 * Cc * Cc];          // [3072,1024] (N,K) fp16
__device__ __half g_wp16[(size_t)Cc * Cc];              // [1024,1024] (N,K) fp16

// q pre-scale: 1/sqrt(64) * log2(e)  (softmax runs in exp2 domain)
#define QSCALE 0.180336880f

// ---------------- helpers ------------------------------------------------
__device__ __forceinline__ uint32_t smem_u32(const void* p) {
    return (uint32_t)__cvta_generic_to_shared(p);
}
__device__ __forceinline__ void cp_async16(uint32_t dst, const void* src) {
    asm volatile("cp.async.cg.shared.global [%0], [%1], 16;\n"
                 :: "r"(dst), "l"(src));
}
#define CP_COMMIT() asm volatile("cp.async.commit_group;\n" ::: "memory")
#define CP_WAIT1()  asm volatile("cp.async.wait_group 1;\n" ::: "memory")

#define LDSM4(r0, r1, r2, r3, addr) \
    asm volatile("ldmatrix.sync.aligned.m8n8.x4.shared.b16 {%0,%1,%2,%3}, [%4];" \
                 : "=r"(r0), "=r"(r1), "=r"(r2), "=r"(r3) : "r"(addr))
#define LDSM4T(r0, r1, r2, r3, addr) \
    asm volatile("ldmatrix.sync.aligned.m8n8.x4.trans.shared.b16 {%0,%1,%2,%3}, [%4];" \
                 : "=r"(r0), "=r"(r1), "=r"(r2), "=r"(r3) : "r"(addr))

// fp16 mma, fp32 accumulate
#define MMAH(d, a, bv0, bv1) \
    asm volatile("mma.sync.aligned.m16n8k16.row.col.f32.f16.f16.f32 " \
                 "{%0,%1,%2,%3}, {%4,%5,%6,%7}, {%8,%9}, {%0,%1,%2,%3};" \
                 : "+f"((d)[0]), "+f"((d)[1]), "+f"((d)[2]), "+f"((d)[3]) \
                 : "r"((a)[0]), "r"((a)[1]), "r"((a)[2]), "r"((a)[3]), \
                   "r"(bv0), "r"(bv1))

__device__ __forceinline__ uint32_t packf16(float hi, float lo) {
    uint32_t d;
    asm("cvt.rn.f16x2.f32 %0, %1, %2;" : "=r"(d) : "f"(hi), "f"(lo));
    return d;
}
__device__ __forceinline__ uint32_t h2exp2(uint32_t x) {
    uint32_t d;
    asm("ex2.approx.f16x2 %0, %1;" : "=r"(d) : "r"(x));
    return d;
}

// ---------------- merged input prep ----------------------------------------
__global__ __launch_bounds__(256)
void prep_inputs(const float4* __restrict__ x4, __half* __restrict__ x16,
                 const float* __restrict__ wa, __half* __restrict__ wa16,
                 const float* __restrict__ wp, __half* __restrict__ wp16)
{
    __shared__ float t[32][33];
    const int bid = blockIdx.x;
    const int tid = threadIdx.x;

    if (bid < 8192) {
        int i = bid * 256 + tid;
        float4 v = x4[i];
        *(uint2*)(x16 + (size_t)i * 4) =
            make_uint2(packf16(v.y, v.x), packf16(v.w, v.z));
        return;
    }

    const float* in;
    __half* o16;
    int N, bx, by;
    if (bid < 11264) {
        int b2 = bid - 8192;
        in = wa; o16 = wa16; N = 3 * Cc;
        bx = b2 % 96; by = b2 / 96;
    } else {
        int b3 = bid - 11264;
        in = wp; o16 = wp16; N = Cc;
        bx = b3 % 32; by = b3 / 32;
    }
    const int tx = tid & 31;
    const int ty = tid >> 5;
    int xg = bx * 32 + tx;
    int yg = by * 32 + ty;
#pragma unroll
    for (int j = 0; j < 32; j += 8)
        t[ty + j][tx] = in[(size_t)(yg + j) * N + xg];
    __syncthreads();
    int xo = by * 32 + tx;
    int yo = bx * 32 + ty;
#pragma unroll
    for (int j = 0; j < 32; j += 8)
        o16[(size_t)(yo + j) * Cc + xo] = __float2half_rn(t[tx][ty + j]);
}

// ---------------- mma.sync fp16 GEMM (converged) ----------------------------
template <int Mdim, int Ndim, int Kdim, int OM>
__global__ __launch_bounds__(256, 2)
void gemm_mma(const __half* __restrict__ A,
              const __half* __restrict__ Bw,
              const float* __restrict__ bias, float* __restrict__ C,
              __half* __restrict__ Ch)
{
    constexpr int NCHUNK = Kdim / 64;
    constexpr uint32_t MATB = 16384;
    constexpr uint32_t STAGE = 32768;

    extern __shared__ char smem[];
    const uint32_t sbase = smem_u32(smem);

    const int tid  = threadIdx.x;
    const int wid  = tid >> 5;
    const int lane = tid & 31;
    const int m0 = blockIdx.y * 128;
    const int n0 = blockIdx.x * 128;
    const int wm = (wid & 3) * 32;
    const int wn = (wid >> 2) * 64;

    const int arow = lane & 15;
    const int ac16 = lane >> 4;
    const int bn   = ((lane >> 4) << 3) + (lane & 7);
    const int bc16 = (lane >> 3) & 1;

    auto swz = [](int row, int c16) -> uint32_t {
        return (uint32_t)row * 128 + (uint32_t)((c16 ^ (row & 7)) << 4);
    };

    auto load_chunk = [&](int c, int st) {
        const int k0 = c * 64;
        const uint32_t sb = sbase + (uint32_t)st * STAGE;
#pragma unroll
        for (int t = 0; t < 8; t++) {
            int i = tid + t * 256;
            int mat = i >> 10;
            int rem = i & 1023;
            int row = rem >> 3, seg = rem & 7;
            uint32_t dst = sb + (uint32_t)mat * MATB + swz(row, seg);
            const __half* src = (mat == 0)
                ? A + (size_t)(m0 + row) * Kdim + k0 + seg * 8
                : Bw + (size_t)(n0 + row) * Kdim + k0 + seg * 8;
            cp_async16(dst, src);
        }
    };

    float acc[2][8][4];
#pragma unroll
    for (int i = 0; i < 2; i++)
#pragma unroll
        for (int j = 0; j < 8; j++)
#pragma unroll
            for (int k = 0; k < 4; k++) acc[i][j][k] = 0.f;

    load_chunk(0, 0); CP_COMMIT();
    load_chunk(1, 1); CP_COMMIT();

    for (int c = 0; c < NCHUNK; c++) {
        CP_WAIT1();
        __syncthreads();
        if (c + 2 < NCHUNK) load_chunk(c + 2, (c + 2) % 3);
        CP_COMMIT();

        const uint32_t sb = sbase + (uint32_t)(c % 3) * STAGE;
        const uint32_t sA = sb, sB = sb + MATB;

        uint32_t af[2][4], bf[8][2];
#pragma unroll
        for (int ks = 0; ks < 4; ks++) {
#pragma unroll
            for (int mf = 0; mf < 2; mf++) {
                int row = wm + mf * 16 + arow;
                uint32_t ra = swz(row, ks * 2 + ac16);
                LDSM4(af[mf][0], af[mf][1], af[mf][2], af[mf][3], sA + ra);
            }
#pragma unroll
            for (int np = 0; np < 4; np++) {
                int row = wn + np * 16 + bn;
                uint32_t rb = swz(row, ks * 2 + bc16);
                LDSM4(bf[np * 2][0], bf[np * 2][1],
                      bf[np * 2 + 1][0], bf[np * 2 + 1][1], sB + rb);
            }
#pragma unroll
            for (int mf = 0; mf < 2; mf++)
#pragma unroll
                for (int nf = 0; nf < 8; nf++)
                    MMAH(acc[mf][nf], af[mf], bf[nf][0], bf[nf][1]);
        }
    }

    const int r0 = lane >> 2;
    const int c0 = (lane & 3) * 2;
#pragma unroll
    for (int mf = 0; mf < 2; mf++) {
#pragma unroll
        for (int nf = 0; nf < 8; nf++) {
            int row = m0 + wm + mf * 16 + r0;
            int col = n0 + wn + nf * 8 + c0;
            float2 b2 = *(const float2*)(bias + col);
            float y00 = acc[mf][nf][0] + b2.x;
            float y01 = acc[mf][nf][1] + b2.y;
            float y10 = acc[mf][nf][2] + b2.x;
            float y11 = acc[mf][nf][3] + b2.y;
            if (OM == 0) {
                *(float2*)(C + (size_t)row * Ndim + col) = make_float2(y00, y01);
                *(float2*)(C + (size_t)(row + 8) * Ndim + col) = make_float2(y10, y11);
            } else {
                float s = (col < Cc) ? QSCALE : 1.0f;
                *(uint32_t*)(Ch + (size_t)row * Ndim + col) =
                    packf16(y01 * s, y00 * s);
                *(uint32_t*)(Ch + (size_t)(row + 8) * Ndim + col) =
                    packf16(y11 * s, y10 * s);
            }
        }
    }
}

// ---------------- flash attention: R15 config (proven best) -----------------
// CTA: one (b, h, 128-row Q block). 256 threads, 8 warps x 16 q rows,
// 2 CTAs/SM. 3-stage KV pipeline, np-skip on diagonal tiles, constant
// ones-column l-fragment. smem = Q(18432) + 3 x (9216+9216) = 73728.
__global__ __launch_bounds__(256, 2)
void flash_f16(const __half* __restrict__ qkv,
               __half* __restrict__ y16)
{
    constexpr uint32_t RSTR = 144;
    constexpr uint32_t TB   = 9216;
    constexpr uint32_t QB   = 18432;
    constexpr uint32_t KVSTG = 2 * TB;

    extern __shared__ char smem[];
    const uint32_t sbase = smem_u32(smem);

    const int tid  = threadIdx.x;
    const int wid  = tid >> 5;
    const int lane = tid & 31;
    const int qt   = (Tt / 128 - 1) - blockIdx.x;
    const int bh   = blockIdx.y;
    const int b    = bh >> 4;
    const int h    = bh & 15;
    const int wm   = wid * 16;
    const int nkv  = 2 * qt + 2;

    const size_t rs = 3 * Cc;
    const size_t rowbase = (size_t)b * Tt;

    auto loadKV = [&](int kt, int st) {
        const uint32_t kb = sbase + QB + (uint32_t)st * KVSTG;
        const uint32_t vb = kb + TB;
#pragma unroll
        for (int i = tid; i < 512; i += 256) {
            int r = i >> 3, s = i & 7;
            uint32_t off = (uint32_t)r * RSTR + s * 16;
            size_t gk = (rowbase + kt * 64 + r) * rs + Cc + h * HDm + s * 8;
            cp_async16(kb + off, qkv + gk);
            cp_async16(vb + off, qkv + gk + Cc);
        }
    };

    {
#pragma unroll
        for (int i = tid; i < 1024; i += 256) {
            int r = i >> 3, s = i & 7;
            uint32_t off = (uint32_t)r * RSTR + s * 16;
            size_t gq = (rowbase + qt * 128 + r) * rs + h * HDm + s * 8;
            cp_async16(sbase + off, qkv + gq);
        }
        loadKV(0, 0);
    }
    CP_COMMIT();
    loadKV(1, 1);
    CP_COMMIT();

    CP_WAIT1();
    __syncthreads();

    uint32_t qf[4][4];
    {
        const int arow = lane & 15;
        const int ak16 = (lane >> 4) * 16;
#pragma unroll
        for (int ks = 0; ks < 4; ks++) {
            uint32_t ra = (uint32_t)(wm + arow) * RSTR + ks * 32 + ak16;
            LDSM4(qf[ks][0], qf[ks][1], qf[ks][2], qf[ks][3], sbase + ra);
        }
    }

    float o[8][4], oL[4];
#pragma unroll
    for (int i = 0; i < 8; i++)
#pragma unroll
        for (int j = 0; j < 4; j++) o[i][j] = 0.f;
#pragma unroll
    for (int j = 0; j < 4; j++) oL[j] = 0.f;

    const int gid = lane >> 2;
    const int tig = lane & 3;
    const int brow = ((lane >> 4) << 3) + (lane & 7);
    const int bk16 = (lane & 8) * 2;
    const int vrow = lane & 15;
    const int vcol16 = (lane >> 4) * 16;

    // constant ones-column B fragment: B[k][0]=1, B[k][1..7]=0 (n = lane>>2)
    const uint32_t wone = (lane < 4) ? 0x3c003c00u : 0u;

    const int rg0 = qt * 128 + wm + gid;
    const int rg1 = rg0 + 8;
    const int rwmax = qt * 128 + wm + 15;

    for (int kt = 0; kt < nkv; kt++) {
        CP_WAIT1();
        __syncthreads();
        if (kt + 2 < nkv) loadKV(kt + 2, (kt + 2) % 3);
        CP_COMMIT();

        const uint32_t sk = sbase + QB + (uint32_t)(kt % 3) * KVSTG;
        const uint32_t sv = sk + TB;

        if (kt * 64 <= rwmax) {      // skip tiles fully above this warp's rows
            const int npLim = (rwmax - kt * 64) >> 4;

            float s[8][4];
#pragma unroll
            for (int i = 0; i < 8; i++)
#pragma unroll
                for (int j = 0; j < 4; j++) s[i][j] = 0.f;

#pragma unroll
            for (int ks = 0; ks < 4; ks++) {
                const uint32_t kb = ks * 32;
#pragma unroll
                for (int np = 0; np < 4; np++) {
                    if (np <= npLim) {
                        uint32_t ro = (uint32_t)(np * 16 + brow) * RSTR + kb + bk16;
                        uint32_t b0, b1, b2, b3;
                        LDSM4(b0, b1, b2, b3, sk + ro);
                        MMAH(s[2 * np], qf[ks], b0, b1);
                        MMAH(s[2 * np + 1], qf[ks], b2, b3);
                    }
                }
            }

            if (kt * 64 + 63 > qt * 128 + wm) {   // diagonal-overlapping tile
#pragma unroll
                for (int nf = 0; nf < 8; nf++) {
                    int cc0 = kt * 64 + nf * 8 + tig * 2;
                    if (cc0 > rg0) s[nf][0] = -1e30f;
                    if (cc0 + 1 > rg0) s[nf][1] = -1e30f;
                    if (cc0 > rg1) s[nf][2] = -1e30f;
                    if (cc0 + 1 > rg1) s[nf][3] = -1e30f;
                }
            }

            // P = exp2(s) in packed fp16; O += P V; l += P @ ones
#pragma unroll
            for (int ks = 0; ks < 4; ks++) {
                uint32_t pf[4];
                pf[0] = h2exp2(packf16(s[2 * ks][1], s[2 * ks][0]));
                pf[1] = h2exp2(packf16(s[2 * ks][3], s[2 * ks][2]));
                pf[2] = h2exp2(packf16(s[2 * ks + 1][1], s[2 * ks + 1][0]));
                pf[3] = h2exp2(packf16(s[2 * ks + 1][3], s[2 * ks + 1][2]));
#pragma unroll
                for (int np = 0; np < 4; np++) {
                    uint32_t vo = (uint32_t)(ks * 16 + vrow) * RSTR + np * 32 + vcol16;
                    uint32_t v0, v1, v2, v3;
                    LDSM4T(v0, v1, v2, v3, sv + vo);
                    MMAH(o[2 * np], pf, v0, v1);
                    MMAH(o[2 * np + 1], pf, v2, v3);
                }
                MMAH(oL, pf, wone, wone);   // l column (constant fragment)
            }
        }
    }

    // broadcast l (held by tig=0 in oL[0]/oL[2]) to the whole row group
    float l0 = __shfl_sync(0xffffffffu, oL[0], (lane >> 2) << 2);
    float l1 = __shfl_sync(0xffffffffu, oL[2], (lane >> 2) << 2);

    float inv0 = 1.0f / l0, inv1 = 1.0f / l1;
    const size_t row0 = rowbase + qt * 128 + wm + gid;
    const int colb = h * HDm + tig * 2;
#pragma unroll
    for (int nh = 0; nh < 8; nh++) {
        int col = colb + nh * 8;
        *(uint32_t*)(y16 + row0 * Cc + col) =
            packf16(o[nh][1] * inv0, o[nh][0] * inv0);
        *(uint32_t*)(y16 + (row0 + 8) * Cc + col) =
            packf16(o[nh][3] * inv1, o[nh][2] * inv1);
    }
}

// ---------------- launch ---------------------------------------------------
extern "C" void kernel_launch(void* const* d_in, const int* in_sizes, int n_in,
                              void* d_out, int out_size)
{
    const float* x      = (const float*)d_in[0];
    const float* w_attn = (const float*)d_in[1];
    const float* b_attn = (const float*)d_in[2];
    const float* w_proj = (const float*)d_in[3];
    const float* b_proj = (const float*)d_in[4];
    float* out = (float*)d_out;

    __half *qkv16, *x16, *y16, *wa16, *wp16;
    cudaGetSymbolAddress((void**)&qkv16, g_qkv16);
    cudaGetSymbolAddress((void**)&x16, g_x16);
    cudaGetSymbolAddress((void**)&y16, g_y16);
    cudaGetSymbolAddress((void**)&wa16, g_wa16);
    cudaGetSymbolAddress((void**)&wp16, g_wp16);

    constexpr int GEMM_SMEM = 3 * 32768;  // 98304 -> 2 CTAs/SM
    cudaFuncSetAttribute(gemm_mma<Bb * Tt, 3 * Cc, Cc, 1>,
                         cudaFuncAttributeMaxDynamicSharedMemorySize, GEMM_SMEM);
    cudaFuncSetAttribute(gemm_mma<Bb * Tt, Cc, Cc, 0>,
                         cudaFuncAttributeMaxDynamicSharedMemorySize, GEMM_SMEM);
    constexpr int FLASH_SMEM = 18432 + 6 * 9216;  // 73728 -> 2 CTAs/SM
    cudaFuncSetAttribute(flash_f16, cudaFuncAttributeMaxDynamicSharedMemorySize,
                         FLASH_SMEM);

    // 0) merged input prep: x->fp16 + both weight transposes (one launch)
    prep_inputs<<<12288, 256>>>((const float4*)x, x16, w_attn, wa16, w_proj, wp16);

    // 1) QKV GEMM (fp16) -> fp16 qkv, q pre-scaled by QSCALE
    gemm_mma<Bb * Tt, 3 * Cc, Cc, 1>
        <<<dim3((3 * Cc) / 128, (Bb * Tt) / 128), 256, GEMM_SMEM>>>(
            x16, wa16, b_attn, nullptr, qkv16);

    // 2) flash attention (fp16, Q tile 128, R15 config) -> fp16 y
    flash_f16<<<dim3(Tt / 128, Bb * Hh), 256, FLASH_SMEM>>>(qkv16, y16);

    // 3) output projection (fp16) -> fp32 out
    gemm_mma<Bb * Tt, Cc, Cc, 0>
        <<<dim3(Cc / 128, (Bb * Tt) / 128), 256, GEMM_SMEM>>>(
            y16, wp16, b_proj, out, nullptr);
}